// round 6
// baseline (speedup 1.0000x reference)
#include <cuda_runtime.h>
#include <cuda_bf16.h>
#include <math.h>
#include <stdint.h>

#define BATCH 8
#define CDIM 256
#define NDIM 16384
#define HEADS 4
#define HD 64
#define SPLIT1 16
#define ATT_SCALE 0.125f
#define LDT 68
#define LDU 36   // u32 pitch per smem row (72 bf16)

// ---------------- scratch ----------------
__device__ unsigned g_xhi[BATCH * CDIM * NDIM / 2];
__device__ unsigned g_xlo[BATCH * CDIM * NDIM / 2];
__device__ unsigned g_xThi[BATCH * NDIM * CDIM / 2];
__device__ unsigned g_xTlo[BATCH * NDIM * CDIM / 2];
__device__ unsigned g_Mhi[BATCH * CDIM * CDIM / 2];
__device__ unsigned g_Mlo[BATCH * CDIM * CDIM / 2];
__device__ float g_Gpart[SPLIT1][BATCH][CDIM][CDIM];
__device__ float g_G[BATCH][CDIM][CDIM];
__device__ float g_r[BATCH][CDIM];
__device__ float g_T1[BATCH][HEADS][HD][CDIM];
__device__ float g_P[BATCH][HEADS][HD][HD];
__device__ float g_U[BATCH][CDIM][CDIM];
__device__ float g_u0[BATCH][CDIM];
__device__ float g_M[BATCH][CDIM][CDIM];
__device__ float g_cb[BATCH][CDIM];

__device__ __forceinline__ unsigned f2bf(float f) {
    __nv_bfloat16 h = __float2bfloat16(f);
    return (unsigned)*reinterpret_cast<unsigned short*>(&h);
}
__device__ __forceinline__ float bf2f(unsigned u) {
    unsigned short s = (unsigned short)u;
    __nv_bfloat16 h = *reinterpret_cast<__nv_bfloat16*>(&s);
    return __bfloat162float(h);
}

__device__ __forceinline__ void mma_bf16(float* c, const unsigned* a, const unsigned* b) {
    asm volatile(
        "mma.sync.aligned.m16n8k16.row.col.f32.bf16.bf16.f32 "
        "{%0,%1,%2,%3}, {%4,%5,%6,%7}, {%8,%9}, {%0,%1,%2,%3};"
        : "+f"(c[0]), "+f"(c[1]), "+f"(c[2]), "+f"(c[3])
        : "r"(a[0]), "r"(a[1]), "r"(a[2]), "r"(a[3]), "r"(b[0]), "r"(b[1]));
}

// one 64-k chunk for one warp; acc[mf][nf][4]
__device__ __forceinline__ void warp_chunk(const unsigned* sAhi, const unsigned* sAlo,
                                           const unsigned* sBhi, const unsigned* sBlo,
                                           float acc[4][4][4], int wy, int wx, int lane) {
    int g = lane >> 2, tg = lane & 3;
#pragma unroll
    for (int ks = 0; ks < 4; ks++) {
        int kb = ks * 8 + tg;
        unsigned ah[4][4], al[4][4], bh[4][2], bl[4][2];
#pragma unroll
        for (int mf = 0; mf < 4; mf++) {
            int r = wy * 64 + mf * 16 + g;
            ah[mf][0] = sAhi[r * LDU + kb];       ah[mf][1] = sAhi[(r + 8) * LDU + kb];
            ah[mf][2] = sAhi[r * LDU + kb + 4];   ah[mf][3] = sAhi[(r + 8) * LDU + kb + 4];
            al[mf][0] = sAlo[r * LDU + kb];       al[mf][1] = sAlo[(r + 8) * LDU + kb];
            al[mf][2] = sAlo[r * LDU + kb + 4];   al[mf][3] = sAlo[(r + 8) * LDU + kb + 4];
        }
#pragma unroll
        for (int nf = 0; nf < 4; nf++) {
            int n = wx * 32 + nf * 8 + g;
            bh[nf][0] = sBhi[n * LDU + kb];  bh[nf][1] = sBhi[n * LDU + kb + 4];
            bl[nf][0] = sBlo[n * LDU + kb];  bl[nf][1] = sBlo[n * LDU + kb + 4];
        }
#pragma unroll
        for (int mf = 0; mf < 4; mf++)
#pragma unroll
            for (int nf = 0; nf < 4; nf++) {
                mma_bf16(acc[mf][nf], ah[mf], bh[nf]);
                mma_bf16(acc[mf][nf], ah[mf], bl[nf]);
                mma_bf16(acc[mf][nf], al[mf], bh[nf]);
            }
    }
}

// ================= KZ: zero g_r =================
__global__ void kz_zero() { ((float*)g_r)[blockIdx.x * 256 + threadIdx.x] = 0.f; }

// ================= K0: x -> bf16 hi/lo (K-major + transposed) + row sums =================
__global__ __launch_bounds__(256) void k0_conv(const float* __restrict__ x) {
    __shared__ float sx[64 * 65];
    int nt = blockIdx.x, ct = blockIdx.y, b = blockIdx.z, tid = threadIdx.x;
    int n0 = nt * 64, c0 = ct * 64;
    int r = tid >> 2, q = tid & 3;
    const float* src = x + (size_t)(b * CDIM + c0 + r) * NDIM + n0 + q * 16;
    float f[16];
#pragma unroll
    for (int m = 0; m < 4; m++) *(float4*)(f + 4 * m) = *(const float4*)(src + 4 * m);
    float rs = 0.f;
    unsigned ph[8], pl[8];
#pragma unroll
    for (int m = 0; m < 16; m += 2) {
        rs += f[m] + f[m + 1];
        unsigned h0 = f2bf(f[m]), h1 = f2bf(f[m + 1]);
        unsigned l0 = f2bf(f[m] - bf2f(h0)), l1 = f2bf(f[m + 1] - bf2f(h1));
        ph[m >> 1] = h0 | (h1 << 16);
        pl[m >> 1] = l0 | (l1 << 16);
        sx[r * 65 + q * 16 + m] = f[m];
        sx[r * 65 + q * 16 + m + 1] = f[m + 1];
    }
    size_t kidx = (size_t)(b * CDIM + c0 + r) * 8192 + ((n0 + q * 16) >> 1);
    *(uint4*)(g_xhi + kidx) = *(uint4*)ph;  *(uint4*)(g_xhi + kidx + 4) = *(uint4*)(ph + 4);
    *(uint4*)(g_xlo + kidx) = *(uint4*)pl;  *(uint4*)(g_xlo + kidx + 4) = *(uint4*)(pl + 4);
    rs += __shfl_down_sync(0xffffffffu, rs, 2);
    rs += __shfl_down_sync(0xffffffffu, rs, 1);
    if (q == 0) atomicAdd(&g_r[b][c0 + r], rs);
    __syncthreads();
    int nr = tid >> 2, cq = tid & 3;
    unsigned th[8], tl[8];
#pragma unroll
    for (int m = 0; m < 16; m += 2) {
        float a = sx[(cq * 16 + m) * 65 + nr];
        float bb = sx[(cq * 16 + m + 1) * 65 + nr];
        unsigned h0 = f2bf(a), h1 = f2bf(bb);
        unsigned l0 = f2bf(a - bf2f(h0)), l1 = f2bf(bb - bf2f(h1));
        th[m >> 1] = h0 | (h1 << 16);
        tl[m >> 1] = l0 | (l1 << 16);
    }
    size_t tix = (size_t)(b * NDIM + n0 + nr) * 128 + (c0 >> 1) + cq * 8;
    *(uint4*)(g_xThi + tix) = *(uint4*)th;  *(uint4*)(g_xThi + tix + 4) = *(uint4*)(th + 4);
    *(uint4*)(g_xTlo + tix) = *(uint4*)tl;  *(uint4*)(g_xTlo + tix + 4) = *(uint4*)(tl + 4);
}

// ================= K1: Gram partials via mma.sync (bf16x3) =================
// grid (3 tiles, SPLIT1, BATCH), 256 threads, dyn smem 73728
__global__ __launch_bounds__(256) void k1_gram() {
    extern __shared__ __align__(16) unsigned S[];
    unsigned* sAhi = S;            unsigned* sAlo = S + 4608;
    unsigned* sBhi = S + 9216;     unsigned* sBlo = S + 13824;
    int tid = threadIdx.x, wid = tid >> 5, lane = tid & 31;
    int tileid = blockIdx.x, s = blockIdx.y, b = blockIdx.z;
    int i0 = (tileid == 2) ? 128 : 0;
    int j0 = (tileid == 0) ? 0 : 128;
    int wy = wid >> 2, wx = wid & 3;
    float acc[4][4][4] = {};
    for (int ch = 0; ch < 16; ch++) {
        __syncthreads();
#pragma unroll 4
        for (int it = 0; it < 64; it++) {
            int u = tid + (it << 8);
            int buf = u >> 12, v = u & 4095, row = v >> 5, kp = v & 31;
            int grow = ((buf & 2) ? j0 : i0) + row;
            const unsigned* gp = (buf & 1) ? g_xlo : g_xhi;
            S[buf * 4608 + row * LDU + kp] =
                gp[(size_t)(b * CDIM + grow) * 8192 + s * 512 + ch * 32 + kp];
        }
        __syncthreads();
        warp_chunk(sAhi, sAlo, sBhi, sBlo, acc, wy, wx, lane);
    }
    int g = lane >> 2, tg = lane & 3;
#pragma unroll
    for (int mf = 0; mf < 4; mf++)
#pragma unroll
        for (int nf = 0; nf < 4; nf++) {
            int row = i0 + wy * 64 + mf * 16 + g;
            int col = j0 + wx * 32 + nf * 8 + 2 * tg;
            *(float2*)&g_Gpart[s][b][row][col] =
                make_float2(acc[mf][nf][0], acc[mf][nf][1]);
            *(float2*)&g_Gpart[s][b][row + 8][col] =
                make_float2(acc[mf][nf][2], acc[mf][nf][3]);
        }
}

// ================= K2: reduce partials -> G (with symmetry fill) =================
__global__ __launch_bounds__(256) void k2_reduce() {
    int i = blockIdx.x, b = blockIdx.y, j = threadIdx.x;
    float acc = 0.f;
    if (i >= 128 && j < 128) {
#pragma unroll
        for (int sp = 0; sp < SPLIT1; sp++) acc += g_Gpart[sp][b][j][i];
    } else {
#pragma unroll
        for (int sp = 0; sp < SPLIT1; sp++) acc += g_Gpart[sp][b][i][j];
    }
    g_G[b][i][j] = acc;
}

// ---------------- fp32 64x64 helpers ----------------
__device__ __forceinline__ void load_tile_T(float* dst, const float* __restrict__ src,
                                            int ld, int tid) {
#pragma unroll
    for (int l = 0; l < 4; l++) {
        int idx = tid + l * 256, row = idx >> 4, kq = (idx & 15) << 2;
        float4 v = *(const float4*)(src + (size_t)row * ld + kq);
        dst[(kq + 0) * LDT + row] = v.x; dst[(kq + 1) * LDT + row] = v.y;
        dst[(kq + 2) * LDT + row] = v.z; dst[(kq + 3) * LDT + row] = v.w;
    }
}
__device__ __forceinline__ void load_tile_N(float* dst, const float* __restrict__ src,
                                            int ld, int tid) {
#pragma unroll
    for (int l = 0; l < 4; l++) {
        int idx = tid + l * 256, row = idx >> 4, cq = (idx & 15) << 2;
        *(float4*)(dst + row * LDT + cq) = *(const float4*)(src + (size_t)row * ld + cq);
    }
}
__device__ __forceinline__ void mm64_step(const float* sA, const float* sB,
                                          float acc[4][4], int ty, int tx) {
#pragma unroll 16
    for (int kk = 0; kk < 64; kk++) {
        float4 a = *(const float4*)(sA + kk * LDT + ty * 4);
        float4 b = *(const float4*)(sB + kk * LDT + tx * 4);
        float av[4] = {a.x, a.y, a.z, a.w}, bv[4] = {b.x, b.y, b.z, b.w};
#pragma unroll
        for (int i = 0; i < 4; i++)
#pragma unroll
            for (int j = 0; j < 4; j++) acc[i][j] += av[i] * bv[j];
    }
}

// ================= K3: T1 = Wq_h @ G_b =================
__global__ __launch_bounds__(256) void k3_t1(const float* __restrict__ Wqkv) {
    __shared__ float smem[2 * 64 * LDT];
    float* sA = smem; float* sB = smem + 64 * LDT;
    int cc = blockIdx.x, h = blockIdx.y, b = blockIdx.z, tid = threadIdx.x;
    int ty = tid >> 4, tx = tid & 15;
    float acc[4][4] = {};
    for (int kc = 0; kc < 4; kc++) {
        load_tile_T(sA, Wqkv + (size_t)(h * HD) * CDIM + kc * 64, CDIM, tid);
        load_tile_N(sB, &g_G[b][kc * 64][cc * 64], CDIM, tid);
        __syncthreads();
        mm64_step(sA, sB, acc, ty, tx);
        __syncthreads();
    }
#pragma unroll
    for (int i = 0; i < 4; i++)
        *(float4*)&g_T1[b][h][ty * 4 + i][cc * 64 + tx * 4] =
            make_float4(acc[i][0], acc[i][1], acc[i][2], acc[i][3]);
}

// ======== K4: S = T1 @ Wk^T + bias terms; softmax -> P, u0 ========
__global__ __launch_bounds__(256) void k4_attn(const float* __restrict__ Wqkv,
                                               const float* __restrict__ bqkv) {
    __shared__ float smem[2 * 64 * LDT];
    __shared__ float sr[CDIM], sqr[HD], srk[HD], sbq[HD], sbk[HD], sbv[HD];
    float* sA = smem; float* sB = smem + 64 * LDT; float* sS = smem;
    int h = blockIdx.x, b = blockIdx.y, tid = threadIdx.x;
    sr[tid] = g_r[b][tid];
    if (tid < HD)          sbq[tid]          = bqkv[h * HD + tid];
    else if (tid < 2 * HD) sbk[tid - HD]     = bqkv[CDIM + h * HD + (tid - HD)];
    else if (tid < 3 * HD) sbv[tid - 2 * HD] = bqkv[2 * CDIM + h * HD + (tid - 2 * HD)];
    __syncthreads();
    if (tid < HD) {
        const float* wr = Wqkv + (size_t)(h * HD + tid) * CDIM;
        float q = 0.f;
        for (int i = 0; i < CDIM; i++) q += wr[i] * sr[i];
        sqr[tid] = q;
    } else if (tid < 2 * HD) {
        const float* wr = Wqkv + (size_t)(CDIM + h * HD + (tid - HD)) * CDIM;
        float q = 0.f;
        for (int i = 0; i < CDIM; i++) q += wr[i] * sr[i];
        srk[tid - HD] = q;
    }
    int ty = tid >> 4, tx = tid & 15;
    float acc[4][4] = {};
    for (int kc = 0; kc < 4; kc++) {
        load_tile_T(sA, &g_T1[b][h][0][kc * 64], CDIM, tid);
        load_tile_T(sB, Wqkv + (size_t)(CDIM + h * HD) * CDIM + kc * 64, CDIM, tid);
        __syncthreads();
        mm64_step(sA, sB, acc, ty, tx);
        __syncthreads();
    }
    float nf = (float)NDIM;
#pragma unroll
    for (int i = 0; i < 4; i++)
#pragma unroll
        for (int j = 0; j < 4; j++) {
            int d = ty * 4 + i, e = tx * 4 + j;
            sS[d * 65 + e] = (acc[i][j] + sbq[d] * srk[e] + sqr[d] * sbk[e]
                              + nf * sbq[d] * sbk[e]) * ATT_SCALE;
        }
    __syncthreads();
    if (tid < HD) {
        int d = tid;
        float mx = -INFINITY;
        for (int e = 0; e < HD; e++) mx = fmaxf(mx, sS[d * 65 + e]);
        float sum = 0.f;
        for (int e = 0; e < HD; e++) { float ex = expf(sS[d * 65 + e] - mx); sS[d * 65 + e] = ex; sum += ex; }
        float inv = 1.f / sum, pbv = 0.f;
        for (int e = 0; e < HD; e++) {
            float p = sS[d * 65 + e] * inv;
            g_P[b][h][d][e] = p;
            pbv += p * sbv[e];
        }
        g_u0[b][h * HD + d] = pbv;
    }
}

// ================= K5: U rows = P_bh @ Wv_h =================
__global__ __launch_bounds__(256) void k5_u(const float* __restrict__ Wqkv) {
    __shared__ float smem[2 * 64 * LDT];
    float* sA = smem; float* sB = smem + 64 * LDT;
    int cc = blockIdx.x, h = blockIdx.y, b = blockIdx.z, tid = threadIdx.x;
    int ty = tid >> 4, tx = tid & 15;
    float acc[4][4] = {};
    load_tile_T(sA, &g_P[b][h][0][0], 64, tid);
    load_tile_N(sB, Wqkv + (size_t)(2 * CDIM + h * HD) * CDIM + cc * 64, CDIM, tid);
    __syncthreads();
    mm64_step(sA, sB, acc, ty, tx);
#pragma unroll
    for (int i = 0; i < 4; i++)
        *(float4*)&g_U[b][h * HD + ty * 4 + i][cc * 64 + tx * 4] =
            make_float4(acc[i][0], acc[i][1], acc[i][2], acc[i][3]);
}

// ================= K6: M_b = Wproj @ U_b =================
__global__ __launch_bounds__(256) void k6_m(const float* __restrict__ Wproj) {
    __shared__ float smem[2 * 64 * LDT];
    float* sA = smem; float* sB = smem + 64 * LDT;
    int cc = blockIdx.x, oc = blockIdx.y, b = blockIdx.z, tid = threadIdx.x;
    int ty = tid >> 4, tx = tid & 15;
    float acc[4][4] = {};
    for (int kc = 0; kc < 4; kc++) {
        load_tile_T(sA, Wproj + (size_t)(oc * 64) * CDIM + kc * 64, CDIM, tid);
        load_tile_N(sB, &g_U[b][kc * 64][cc * 64], CDIM, tid);
        __syncthreads();
        mm64_step(sA, sB, acc, ty, tx);
        __syncthreads();
    }
#pragma unroll
    for (int i = 0; i < 4; i++)
        *(float4*)&g_M[b][oc * 64 + ty * 4 + i][cc * 64 + tx * 4] =
            make_float4(acc[i][0], acc[i][1], acc[i][2], acc[i][3]);
}

// ================= K6b: c_b = Wproj @ u0_b + bproj =================
__global__ __launch_bounds__(256) void k6b_c(const float* __restrict__ Wproj,
                                             const float* __restrict__ bproj) {
    __shared__ float su[CDIM];
    int b = blockIdx.x, o = threadIdx.x;
    su[o] = g_u0[b][o];
    __syncthreads();
    const float* wr = Wproj + (size_t)o * CDIM;
    float s = 0.f;
#pragma unroll 8
    for (int m = 0; m < CDIM; m++) s += wr[m] * su[m];
    g_cb[b][o] = s + bproj[o];
}

// ================= K6c: M -> bf16 hi/lo =================
__global__ __launch_bounds__(256) void k6c_conv() {
    int t = blockIdx.x * 256 + threadIdx.x;
    float m = ((const float*)g_M)[t];
    unsigned h = f2bf(m), l = f2bf(m - bf2f(h));
    ((unsigned short*)g_Mhi)[t] = (unsigned short)h;
    ((unsigned short*)g_Mlo)[t] = (unsigned short)l;
}

// ================= K7: out = M @ x + c via mma.sync (bf16x3) =================
// grid (NDIM/128, 2, BATCH), 256 threads, dyn smem 74240
__global__ __launch_bounds__(256) void k7_out(float* __restrict__ out) {
    extern __shared__ __align__(16) unsigned S[];
    unsigned* sAhi = S;            unsigned* sAlo = S + 4608;
    unsigned* sBhi = S + 9216;     unsigned* sBlo = S + 13824;
    float* sc = (float*)(S + 18432);
    int tid = threadIdx.x, wid = tid >> 5, lane = tid & 31;
    int nt = blockIdx.x, ot = blockIdx.y, b = blockIdx.z;
    int n0 = nt * 128, o0 = ot * 128;
    if (tid < 128) sc[tid] = g_cb[b][o0 + tid];
    int wy = wid >> 2, wx = wid & 3;
    float acc[4][4][4] = {};
    for (int ch = 0; ch < 4; ch++) {
        __syncthreads();
#pragma unroll 4
        for (int it = 0; it < 64; it++) {
            int u = tid + (it << 8);
            int buf = u >> 12, v = u & 4095, row = v >> 5, kp = v & 31;
            unsigned val;
            if (buf < 2) {
                const unsigned* gp = (buf & 1) ? g_Mlo : g_Mhi;
                val = gp[(size_t)(b * CDIM + o0 + row) * 128 + ch * 32 + kp];
            } else {
                const unsigned* gp = (buf & 1) ? g_xTlo : g_xThi;
                val = gp[(size_t)(b * NDIM + n0 + row) * 128 + ch * 32 + kp];
            }
            S[buf * 4608 + row * LDU + kp] = val;
        }
        __syncthreads();
        warp_chunk(sAhi, sAlo, sBhi, sBlo, acc, wy, wx, lane);
    }
    int g = lane >> 2, tg = lane & 3;
#pragma unroll
    for (int mf = 0; mf < 4; mf++) {
        int ol = wy * 64 + mf * 16 + g;
#pragma unroll
        for (int nf = 0; nf < 4; nf++) {
            int col = n0 + wx * 32 + nf * 8 + 2 * tg;
            float* d0 = out + (size_t)(b * CDIM + o0 + ol) * NDIM + col;
            float* d1 = out + (size_t)(b * CDIM + o0 + ol + 8) * NDIM + col;
            *(float2*)d0 = make_float2(acc[mf][nf][0] + sc[ol], acc[mf][nf][1] + sc[ol]);
            *(float2*)d1 = make_float2(acc[mf][nf][2] + sc[ol + 8], acc[mf][nf][3] + sc[ol + 8]);
        }
    }
}

extern "C" void kernel_launch(void* const* d_in, const int* in_sizes, int n_in,
                              void* d_out, int out_size) {
    const float* x     = (const float*)d_in[0];
    const float* Wqkv  = (const float*)d_in[1];
    const float* bqkv  = (const float*)d_in[2];
    const float* Wproj = (const float*)d_in[3];
    const float* bproj = (const float*)d_in[4];
    float* out = (float*)d_out;

    cudaFuncSetAttribute(k1_gram, cudaFuncAttributeMaxDynamicSharedMemorySize, 73728);
    cudaFuncSetAttribute(k7_out, cudaFuncAttributeMaxDynamicSharedMemorySize, 74240);

    kz_zero<<<8, 256>>>();
    k0_conv<<<dim3(NDIM / 64, CDIM / 64, BATCH), 256>>>(x);
    k1_gram<<<dim3(3, SPLIT1, BATCH), 256, 73728>>>();
    k2_reduce<<<dim3(CDIM, BATCH), 256>>>();
    k3_t1<<<dim3(4, HEADS, BATCH), 256>>>(Wqkv);
    k4_attn<<<dim3(HEADS, BATCH), 256>>>(Wqkv, bqkv);
    k5_u<<<dim3(4, HEADS, BATCH), 256>>>(Wqkv);
    k6_m<<<dim3(4, 4, BATCH), 256>>>(Wproj);
    k6b_c<<<BATCH, 256>>>(Wproj, bproj);
    k6c_conv<<<BATCH * CDIM * CDIM / 256, 256>>>();
    k7_out<<<dim3(NDIM / 128, 2, BATCH), 256, 74240>>>(out);
}